// round 6
// baseline (speedup 1.0000x reference)
#include <cuda_runtime.h>
#include <cstdint>

#define N_NODES 100000
#define N_EDGES 1600000
#define HID     128
#define NH      12800000      // N_NODES * HID
#define SCAN_T  1024
#define PER_T   ((N_NODES + SCAN_T - 1) / SCAN_T)   // 98

typedef unsigned long long u64;

// ---------------- scratch (__device__ globals: no runtime allocation) -------
__device__ float g_dinv[N_NODES];
__device__ int   g_cnt[N_NODES];          // static zero-init; re-zeroed each replay
__device__ int   g_rowptr[N_NODES + 1];
__device__ int   g_cursor[N_NODES];
__device__ int2  g_ecc[N_EDGES];          // (src, coef-as-int) interleaved
__device__ float g_agg[NH];
__device__ float g_h1[NH];
__device__ float g_mu[NH];
__device__ float g_lv[NH];

// ---------------- degree ----------------------------------------------------
__global__ void k_degree(const int* __restrict__ dst) {
    int i = blockIdx.x * 256 + threadIdx.x;
    if (i < N_EDGES) atomicAdd(&g_cnt[dst[i]], 1);
}

// ---------------- fused: dinv + exclusive scan + cursor + cnt re-zero -------
__global__ __launch_bounds__(SCAN_T) void k_scan_fused() {
    __shared__ int sh[SCAN_T];
    int t = threadIdx.x;
    int base = t * PER_T;

    int sum = 0;
    for (int q = 0; q < PER_T; q++) {
        int i = base + q;
        if (i < N_NODES) sum += g_cnt[i];
    }
    sh[t] = sum;
    __syncthreads();
#pragma unroll
    for (int off = 1; off < SCAN_T; off <<= 1) {
        int v = (t >= off) ? sh[t - off] : 0;
        __syncthreads();
        sh[t] += v;
        __syncthreads();
    }
    int run = sh[t] - sum;            // exclusive prefix for this thread's range

    for (int q = 0; q < PER_T; q++) {
        int i = base + q;
        if (i >= N_NODES) break;
        int c = g_cnt[i];
        g_rowptr[i] = run;
        g_cursor[i] = run;
        g_dinv[i]   = rsqrtf((float)c + 1.0f);
        g_cnt[i]    = 0;              // ready for next replay
        run += c;
    }
    if (t == 0) g_rowptr[N_NODES] = N_EDGES;
}

// ---------------- CSR fill ---------------------------------------------------
__global__ void k_fill(const int* __restrict__ src, const int* __restrict__ dst) {
    int e = blockIdx.x * 256 + threadIdx.x;
    if (e >= N_EDGES) return;
    int d = dst[e], s = src[e];
    int pos = atomicAdd(&g_cursor[d], 1);
    float c = g_dinv[s] * g_dinv[d];
    g_ecc[pos] = make_int2(s, __float_as_int(c));
}

// ---------------- CSR aggregation: agg = A_norm @ feat ----------------------
// 2 warps per node; lane owns float2 (8B); groups of 8 edges for MLP=8.
__global__ __launch_bounds__(256) void k_agg(const float* __restrict__ feat,
                                             float* __restrict__ agg) {
    int gw   = (blockIdx.x * 256 + threadIdx.x) >> 5;
    int node = gw >> 1;
    int half = gw & 1;
    int lane = threadIdx.x & 31;
    if (node >= N_NODES) return;

    int beg = g_rowptr[node];
    int end = g_rowptr[node + 1];
    float di = g_dinv[node];
    float sc = di * di;

    const float2* fp = (const float2*)feat;       // 64 float2 per node row
    int off = half * 32 + lane;                   // float2 index within row

    float2 acc = fp[(size_t)node * 64 + off];
    acc.x *= sc; acc.y *= sc;

    int j = beg;
    for (; j + 8 <= end; j += 8) {
        int2 m[8];
#pragma unroll
        for (int q = 0; q < 8; q++) m[q] = g_ecc[j + q];
        float2 v[8];
#pragma unroll
        for (int q = 0; q < 8; q++)
            v[q] = fp[(size_t)m[q].x * 64 + off];
#pragma unroll
        for (int q = 0; q < 8; q++) {
            float c = __int_as_float(m[q].y);
            acc.x = fmaf(c, v[q].x, acc.x);
            acc.y = fmaf(c, v[q].y, acc.y);
        }
    }
    for (; j + 2 <= end; j += 2) {
        int2 m0 = g_ecc[j], m1 = g_ecc[j + 1];
        float2 v0 = fp[(size_t)m0.x * 64 + off];
        float2 v1 = fp[(size_t)m1.x * 64 + off];
        float c0 = __int_as_float(m0.y), c1 = __int_as_float(m1.y);
        acc.x = fmaf(c0, v0.x, acc.x); acc.y = fmaf(c0, v0.y, acc.y);
        acc.x = fmaf(c1, v1.x, acc.x); acc.y = fmaf(c1, v1.y, acc.y);
    }
    if (j < end) {
        int2 m0 = g_ecc[j];
        float2 v0 = fp[(size_t)m0.x * 64 + off];
        float c0 = __int_as_float(m0.y);
        acc.x = fmaf(c0, v0.x, acc.x); acc.y = fmaf(c0, v0.y, acc.y);
    }
    ((float2*)agg)[(size_t)node * 64 + off] = acc;
}

// ---------------- packed f32x2 GEMM helpers ---------------------------------
__device__ __forceinline__ u64 fma2(u64 a, u64 b, u64 c) {
    u64 d;
    asm("fma.rn.f32x2 %0, %1, %2, %3;" : "=l"(d) : "l"(a), "l"(b), "l"(c));
    return d;
}
__device__ __forceinline__ u64 add2(u64 a, u64 b) {
    u64 d;
    asm("add.rn.f32x2 %0, %1, %2;" : "=l"(d) : "l"(a), "l"(b));
    return d;
}
__device__ __forceinline__ u64 dup2(float f) {
    unsigned u = __float_as_uint(f);
    return ((u64)u << 32) | u;
}

// ------- JAX-exact RNG: PARTITIONABLE threefry2x32 + XLA erfinv -------------
__device__ __forceinline__ uint32_t rotl32(uint32_t x, int d) {
    return (x << d) | (x >> (32 - d));
}
__device__ __forceinline__ uint32_t threefry_bits_0_42(uint32_t x0, uint32_t x1) {
    const uint32_t k0 = 0u, k1 = 42u;
    const uint32_t k2 = k0 ^ k1 ^ 0x1BD11BDAu;
    x0 += k0; x1 += k1;
#define TF_RND(r) { x0 += x1; x1 = rotl32(x1, r); x1 ^= x0; }
    TF_RND(13) TF_RND(15) TF_RND(26) TF_RND(6)
    x0 += k1; x1 += k2 + 1u;
    TF_RND(17) TF_RND(29) TF_RND(16) TF_RND(24)
    x0 += k2; x1 += k0 + 2u;
    TF_RND(13) TF_RND(15) TF_RND(26) TF_RND(6)
    x0 += k0; x1 += k1 + 3u;
    TF_RND(17) TF_RND(29) TF_RND(16) TF_RND(24)
    x0 += k1; x1 += k2 + 4u;
    TF_RND(13) TF_RND(15) TF_RND(26) TF_RND(6)
    x0 += k2; x1 += k0 + 5u;
#undef TF_RND
    return x0 ^ x1;      // 32-bit XOR-fold (partitionable path)
}
__device__ __forceinline__ float erfinv_xla(float x) {
    float w = -log1pf(-x * x);
    float p;
    if (w < 5.0f) {
        w -= 2.5f;
        p = 2.81022636e-08f;
        p = fmaf(p, w, 3.43273939e-07f);
        p = fmaf(p, w, -3.5233877e-06f);
        p = fmaf(p, w, -4.39150654e-06f);
        p = fmaf(p, w, 0.00021858087f);
        p = fmaf(p, w, -0.00125372503f);
        p = fmaf(p, w, -0.00417768164f);
        p = fmaf(p, w, 0.246640727f);
        p = fmaf(p, w, 1.50140941f);
    } else {
        w = sqrtf(w) - 3.0f;
        p = -0.000200214257f;
        p = fmaf(p, w, 0.000100950558f);
        p = fmaf(p, w, 0.00134934322f);
        p = fmaf(p, w, -0.00367342844f);
        p = fmaf(p, w, 0.00573950773f);
        p = fmaf(p, w, -0.0076224613f);
        p = fmaf(p, w, 0.00943887047f);
        p = fmaf(p, w, 1.00167406f);
        p = fmaf(p, w, 2.83297682f);
    }
    return p * x;
}
__device__ __forceinline__ float bits_to_normal(uint32_t bits) {
    float u01 = __uint_as_float((bits >> 9) | 0x3f800000u) - 1.0f;
    const float lo = -0.99999994f;
    float u = fmaf(u01, 2.0f, lo);
    u = fmaxf(u, lo);
    return 1.41421356237f * erfinv_xla(u);
}

// C = A@W + b (opt ELU); mirror: optional second copy of C;
// do_rep: z = mu + eps*exp(0.5*C) into z_out, mu read from mu_in (device scratch).
__global__ __launch_bounds__(256) void k_gemm2(const float* __restrict__ A,
                                               const float* __restrict__ W,
                                               const float* __restrict__ bias,
                                               float* __restrict__ C,
                                               float* __restrict__ mirror,
                                               const float* __restrict__ mu_in,
                                               float* __restrict__ z_out,
                                               int act, int do_rep) {
    extern __shared__ float sm[];
    float* xs = sm;                              // [k*132 + r]
    u64*   wd = (u64*)(sm + 128 * 132);          // duplicated pairs [k*128 + c]

    int row0 = blockIdx.x << 7;

    for (int i = threadIdx.x; i < 4096; i += 256) {
        int r  = i & 127;
        int c4 = i >> 7;
        float4 v = make_float4(0.f, 0.f, 0.f, 0.f);
        if (row0 + r < N_NODES)
            v = *(const float4*)(A + (size_t)(row0 + r) * HID + (c4 << 2));
        int k = c4 << 2;
        xs[(k + 0) * 132 + r] = v.x;
        xs[(k + 1) * 132 + r] = v.y;
        xs[(k + 2) * 132 + r] = v.z;
        xs[(k + 3) * 132 + r] = v.w;
    }
    for (int i = threadIdx.x; i < 4096; i += 256) {
        float4 v = ((const float4*)W)[i];
        int b = i << 2;
        wd[b + 0] = dup2(v.x);
        wd[b + 1] = dup2(v.y);
        wd[b + 2] = dup2(v.z);
        wd[b + 3] = dup2(v.w);
    }
    __syncthreads();

    int tx = threadIdx.x & 15;
    int ty = threadIdx.x >> 4;

    u64 acc[4][8];
#pragma unroll
    for (int i2 = 0; i2 < 4; i2++)
#pragma unroll
        for (int jj = 0; jj < 8; jj++) acc[i2][jj] = 0ull;

    const u64* xsd = (const u64*)xs;             // 66 u64 per k

#pragma unroll 4
    for (int k = 0; k < 128; k++) {
        u64 a2[4];
#pragma unroll
        for (int i2 = 0; i2 < 4; i2++)
            a2[i2] = xsd[k * 66 + ty + 16 * i2];
#pragma unroll
        for (int jj = 0; jj < 8; jj++) {
            u64 w2 = wd[(k << 7) + tx + 16 * jj];
#pragma unroll
            for (int i2 = 0; i2 < 4; i2++)
                acc[i2][jj] = fma2(a2[i2], w2, acc[i2][jj]);
        }
    }

    u64 bv2[8];
#pragma unroll
    for (int jj = 0; jj < 8; jj++) bv2[jj] = dup2(bias[tx + 16 * jj]);
#pragma unroll
    for (int i2 = 0; i2 < 4; i2++)
#pragma unroll
        for (int jj = 0; jj < 8; jj++) acc[i2][jj] = add2(acc[i2][jj], bv2[jj]);

#pragma unroll
    for (int i2 = 0; i2 < 4; i2++) {
        int p = ty + 16 * i2;
#pragma unroll
        for (int e = 0; e < 2; e++) {
            int r = row0 + 2 * p + e;
            if (r >= N_NODES) continue;
#pragma unroll
            for (int jj = 0; jj < 8; jj++) {
                unsigned u = (unsigned)(e ? (acc[i2][jj] >> 32)
                                          : (acc[i2][jj] & 0xffffffffull));
                float v = __uint_as_float(u);
                if (act) v = (v > 0.f) ? v : expm1f(v);
                int c = tx + 16 * jj;
                size_t idx = (size_t)r * HID + c;
                C[idx] = v;
                if (mirror) mirror[idx] = v;
                if (do_rep) {
                    uint32_t bits = threefry_bits_0_42(0u, (uint32_t)idx);
                    float eps = bits_to_normal(bits);
                    z_out[idx] = mu_in[idx] + eps * expf(0.5f * v);
                }
            }
        }
    }
}

// ---------------- launch -----------------------------------------------------
extern "C" void kernel_launch(void* const* d_in, const int* in_sizes, int n_in,
                              void* d_out, int out_size) {
    const float* x   = (const float*)d_in[0];
    const int*   ei  = (const int*)d_in[1];
    const float* W1  = (const float*)d_in[2];
    const float* b1  = (const float*)d_in[3];
    const float* Wmu = (const float*)d_in[4];
    const float* bmu = (const float*)d_in[5];
    const float* Wlv = (const float*)d_in[6];
    const float* blv = (const float*)d_in[7];
    float* out = (float*)d_out;

    const int* src = ei;
    const int* dst = ei + N_EDGES;

    void *p_agg, *p_h1, *p_mu, *p_lv;
    cudaGetSymbolAddress(&p_agg, g_agg);
    cudaGetSymbolAddress(&p_h1,  g_h1);
    cudaGetSymbolAddress(&p_mu,  g_mu);
    cudaGetSymbolAddress(&p_lv,  g_lv);

    int big = (out_size >= 3 * NH);
    float* mu_mirror = big ? (out + NH)     : nullptr;   // mu copy into output
    float* lv_dst    = big ? (out + 2 * NH) : (float*)p_lv;

    const size_t gemm_smem = 128 * 132 * sizeof(float) + 128 * 128 * sizeof(u64);
    cudaFuncSetAttribute(k_gemm2, cudaFuncAttributeMaxDynamicSharedMemorySize,
                         (int)gemm_smem);   // 198,656 B

    const int nb_edges = (N_EDGES + 255) / 256;      // 6250
    const int nb_agg   = (N_NODES * 64 + 255) / 256; // 25000 (2 warps/node)
    const int nb_gemm  = (N_NODES + 127) / 128;      // 782

    // L0..L2: degree + fused scan + CSR fill  (g_cnt/g_cursor self-reset)
    k_degree<<<nb_edges, 256>>>(dst);
    k_scan_fused<<<1, SCAN_T>>>();
    k_fill<<<nb_edges, 256>>>(src, dst);

    // L3 (profiled): layer-1 aggregation
    k_agg<<<nb_agg, 256>>>(x, (float*)p_agg);
    // L4: h1 = elu(agg @ W1 + b1)
    k_gemm2<<<nb_gemm, 256, gemm_smem>>>((const float*)p_agg, W1, b1,
                                         (float*)p_h1, nullptr, nullptr, nullptr, 1, 0);
    // L5: layer-2 aggregation
    k_agg<<<nb_agg, 256>>>((const float*)p_h1, (float*)p_agg);
    // L6: mu (device scratch + mirrored into out)
    k_gemm2<<<nb_gemm, 256, gemm_smem>>>((const float*)p_agg, Wmu, bmu,
                                         (float*)p_mu, mu_mirror, nullptr, nullptr, 0, 0);
    // L7: lv + fused reparam (mu read from device scratch)
    k_gemm2<<<nb_gemm, 256, gemm_smem>>>((const float*)p_agg, Wlv, blv,
                                         lv_dst, nullptr, (const float*)p_mu, out, 0, 1);
}

// round 7
// speedup vs baseline: 1.2509x; 1.2509x over previous
#include <cuda_runtime.h>
#include <cstdint>

#define N_NODES 100000
#define N_EDGES 1600000
#define HID     128
#define NH      12800000      // N_NODES * HID
#define NB_SCAN 391           // ceil(N_NODES/256)

typedef unsigned long long u64;

// ---------------- scratch (__device__ globals: no runtime allocation) -------
__device__ float g_dinv[N_NODES];
__device__ int   g_cnt[N_NODES];
__device__ int   g_rowptr[N_NODES + 1];
__device__ int   g_cursor[N_NODES];
__device__ int2  g_ecc[N_EDGES];          // (src, coef-as-int) interleaved
__device__ int   g_bsum[512];
__device__ int   g_boff[512];
__device__ float g_agg[NH];
__device__ float g_h1[NH];
__device__ float g_mu[NH];
__device__ float g_lv[NH];

// ---------------- degree / norm (coalesced, multi-block) --------------------
__global__ void k_zero_cnt() {
    int i = blockIdx.x * 256 + threadIdx.x;
    if (i < N_NODES) g_cnt[i] = 0;
}
__global__ void k_degree(const int* __restrict__ dst) {
    int i = blockIdx.x * 256 + threadIdx.x;
    if (i < N_EDGES) atomicAdd(&g_cnt[dst[i]], 1);
}
__global__ void k_dinv() {
    int i = blockIdx.x * 256 + threadIdx.x;
    if (i < N_NODES) g_dinv[i] = rsqrtf((float)g_cnt[i] + 1.0f);
}

// ---------------- CSR build: block scan + fixup (all coalesced) -------------
__global__ void k_scan1() {
    __shared__ int sh[256];
    int tid = threadIdx.x;
    int i = blockIdx.x * 256 + tid;
    int v = (i < N_NODES) ? g_cnt[i] : 0;
    sh[tid] = v;
    __syncthreads();
#pragma unroll
    for (int off = 1; off < 256; off <<= 1) {
        int t = (tid >= off) ? sh[tid - off] : 0;
        __syncthreads();
        sh[tid] += t;
        __syncthreads();
    }
    if (i < N_NODES) g_rowptr[i] = sh[tid] - v;      // block-local exclusive
    if (tid == 255) g_bsum[blockIdx.x] = sh[255];
}
__global__ void k_scan2() {   // single block, 512 threads (tiny)
    __shared__ int sh[512];
    int tid = threadIdx.x;
    int v = (tid < NB_SCAN) ? g_bsum[tid] : 0;
    sh[tid] = v;
    __syncthreads();
#pragma unroll
    for (int off = 1; off < 512; off <<= 1) {
        int t = (tid >= off) ? sh[tid - off] : 0;
        __syncthreads();
        sh[tid] += t;
        __syncthreads();
    }
    g_boff[tid] = sh[tid] - v;                        // exclusive block offsets
    if (tid == 0) g_rowptr[N_NODES] = N_EDGES;
}
__global__ void k_scan3() {
    int i = blockIdx.x * 256 + threadIdx.x;
    if (i < N_NODES) {
        int r = g_rowptr[i] + g_boff[i >> 8];
        g_rowptr[i] = r;
        g_cursor[i] = r;
    }
}
__global__ void k_fill(const int* __restrict__ src, const int* __restrict__ dst) {
    int e = blockIdx.x * 256 + threadIdx.x;
    if (e >= N_EDGES) return;
    int d = dst[e], s = src[e];
    int pos = atomicAdd(&g_cursor[d], 1);
    float c = g_dinv[s] * g_dinv[d];
    g_ecc[pos] = make_int2(s, __float_as_int(c));
}

// ---------------- CSR aggregation: agg = A_norm @ feat ----------------------
// 2 warps per node; lane owns float2 (8B); groups of 8 edges for MLP=8.
// (measured round 6: 74.2 us per pass)
__global__ __launch_bounds__(256) void k_agg(const float* __restrict__ feat,
                                             float* __restrict__ agg) {
    int gw   = (blockIdx.x * 256 + threadIdx.x) >> 5;
    int node = gw >> 1;
    int half = gw & 1;
    int lane = threadIdx.x & 31;
    if (node >= N_NODES) return;

    int beg = g_rowptr[node];
    int end = g_rowptr[node + 1];
    float di = g_dinv[node];
    float sc = di * di;

    const float2* fp = (const float2*)feat;       // 64 float2 per node row
    int off = half * 32 + lane;                   // float2 index within row

    float2 acc = fp[(size_t)node * 64 + off];
    acc.x *= sc; acc.y *= sc;

    int j = beg;
    for (; j + 8 <= end; j += 8) {
        int2 m[8];
#pragma unroll
        for (int q = 0; q < 8; q++) m[q] = g_ecc[j + q];
        float2 v[8];
#pragma unroll
        for (int q = 0; q < 8; q++)
            v[q] = fp[(size_t)m[q].x * 64 + off];
#pragma unroll
        for (int q = 0; q < 8; q++) {
            float c = __int_as_float(m[q].y);
            acc.x = fmaf(c, v[q].x, acc.x);
            acc.y = fmaf(c, v[q].y, acc.y);
        }
    }
    for (; j + 2 <= end; j += 2) {
        int2 m0 = g_ecc[j], m1 = g_ecc[j + 1];
        float2 v0 = fp[(size_t)m0.x * 64 + off];
        float2 v1 = fp[(size_t)m1.x * 64 + off];
        float c0 = __int_as_float(m0.y), c1 = __int_as_float(m1.y);
        acc.x = fmaf(c0, v0.x, acc.x); acc.y = fmaf(c0, v0.y, acc.y);
        acc.x = fmaf(c1, v1.x, acc.x); acc.y = fmaf(c1, v1.y, acc.y);
    }
    if (j < end) {
        int2 m0 = g_ecc[j];
        float2 v0 = fp[(size_t)m0.x * 64 + off];
        float c0 = __int_as_float(m0.y);
        acc.x = fmaf(c0, v0.x, acc.x); acc.y = fmaf(c0, v0.y, acc.y);
    }
    ((float2*)agg)[(size_t)node * 64 + off] = acc;
}

// ---------------- packed f32x2 GEMM helpers ---------------------------------
__device__ __forceinline__ u64 fma2(u64 a, u64 b, u64 c) {
    u64 d;
    asm("fma.rn.f32x2 %0, %1, %2, %3;" : "=l"(d) : "l"(a), "l"(b), "l"(c));
    return d;
}
__device__ __forceinline__ u64 add2(u64 a, u64 b) {
    u64 d;
    asm("add.rn.f32x2 %0, %1, %2;" : "=l"(d) : "l"(a), "l"(b));
    return d;
}
__device__ __forceinline__ u64 dup2(float f) {
    unsigned u = __float_as_uint(f);
    return ((u64)u << 32) | u;
}

// ------- JAX-exact RNG: PARTITIONABLE threefry2x32 + XLA erfinv -------------
__device__ __forceinline__ uint32_t rotl32(uint32_t x, int d) {
    return (x << d) | (x >> (32 - d));
}
__device__ __forceinline__ uint32_t threefry_bits_0_42(uint32_t x0, uint32_t x1) {
    const uint32_t k0 = 0u, k1 = 42u;
    const uint32_t k2 = k0 ^ k1 ^ 0x1BD11BDAu;
    x0 += k0; x1 += k1;
#define TF_RND(r) { x0 += x1; x1 = rotl32(x1, r); x1 ^= x0; }
    TF_RND(13) TF_RND(15) TF_RND(26) TF_RND(6)
    x0 += k1; x1 += k2 + 1u;
    TF_RND(17) TF_RND(29) TF_RND(16) TF_RND(24)
    x0 += k2; x1 += k0 + 2u;
    TF_RND(13) TF_RND(15) TF_RND(26) TF_RND(6)
    x0 += k0; x1 += k1 + 3u;
    TF_RND(17) TF_RND(29) TF_RND(16) TF_RND(24)
    x0 += k1; x1 += k2 + 4u;
    TF_RND(13) TF_RND(15) TF_RND(26) TF_RND(6)
    x0 += k2; x1 += k0 + 5u;
#undef TF_RND
    return x0 ^ x1;      // 32-bit XOR-fold (partitionable path)
}
__device__ __forceinline__ float erfinv_xla(float x) {
    float w = -log1pf(-x * x);
    float p;
    if (w < 5.0f) {
        w -= 2.5f;
        p = 2.81022636e-08f;
        p = fmaf(p, w, 3.43273939e-07f);
        p = fmaf(p, w, -3.5233877e-06f);
        p = fmaf(p, w, -4.39150654e-06f);
        p = fmaf(p, w, 0.00021858087f);
        p = fmaf(p, w, -0.00125372503f);
        p = fmaf(p, w, -0.00417768164f);
        p = fmaf(p, w, 0.246640727f);
        p = fmaf(p, w, 1.50140941f);
    } else {
        w = sqrtf(w) - 3.0f;
        p = -0.000200214257f;
        p = fmaf(p, w, 0.000100950558f);
        p = fmaf(p, w, 0.00134934322f);
        p = fmaf(p, w, -0.00367342844f);
        p = fmaf(p, w, 0.00573950773f);
        p = fmaf(p, w, -0.0076224613f);
        p = fmaf(p, w, 0.00943887047f);
        p = fmaf(p, w, 1.00167406f);
        p = fmaf(p, w, 2.83297682f);
    }
    return p * x;
}
__device__ __forceinline__ float bits_to_normal(uint32_t bits) {
    float u01 = __uint_as_float((bits >> 9) | 0x3f800000u) - 1.0f;
    const float lo = -0.99999994f;
    float u = fmaf(u01, 2.0f, lo);
    u = fmaxf(u, lo);
    return 1.41421356237f * erfinv_xla(u);
}

// C = A@W + b (opt ELU); mirror: optional second copy of C;
// do_rep: z = mu + eps*exp(0.5*C) into z_out, mu read from mu_in (device scratch).
__global__ __launch_bounds__(256) void k_gemm2(const float* __restrict__ A,
                                               const float* __restrict__ W,
                                               const float* __restrict__ bias,
                                               float* __restrict__ C,
                                               float* __restrict__ mirror,
                                               const float* __restrict__ mu_in,
                                               float* __restrict__ z_out,
                                               int act, int do_rep) {
    extern __shared__ float sm[];
    float* xs = sm;                              // [k*132 + r]
    u64*   wd = (u64*)(sm + 128 * 132);          // duplicated pairs [k*128 + c]

    int row0 = blockIdx.x << 7;

    for (int i = threadIdx.x; i < 4096; i += 256) {
        int r  = i & 127;
        int c4 = i >> 7;
        float4 v = make_float4(0.f, 0.f, 0.f, 0.f);
        if (row0 + r < N_NODES)
            v = *(const float4*)(A + (size_t)(row0 + r) * HID + (c4 << 2));
        int k = c4 << 2;
        xs[(k + 0) * 132 + r] = v.x;
        xs[(k + 1) * 132 + r] = v.y;
        xs[(k + 2) * 132 + r] = v.z;
        xs[(k + 3) * 132 + r] = v.w;
    }
    for (int i = threadIdx.x; i < 4096; i += 256) {
        float4 v = ((const float4*)W)[i];
        int b = i << 2;
        wd[b + 0] = dup2(v.x);
        wd[b + 1] = dup2(v.y);
        wd[b + 2] = dup2(v.z);
        wd[b + 3] = dup2(v.w);
    }
    __syncthreads();

    int tx = threadIdx.x & 15;
    int ty = threadIdx.x >> 4;

    u64 acc[4][8];
#pragma unroll
    for (int i2 = 0; i2 < 4; i2++)
#pragma unroll
        for (int jj = 0; jj < 8; jj++) acc[i2][jj] = 0ull;

    const u64* xsd = (const u64*)xs;             // 66 u64 per k

#pragma unroll 4
    for (int k = 0; k < 128; k++) {
        u64 a2[4];
#pragma unroll
        for (int i2 = 0; i2 < 4; i2++)
            a2[i2] = xsd[k * 66 + ty + 16 * i2];
#pragma unroll
        for (int jj = 0; jj < 8; jj++) {
            u64 w2 = wd[(k << 7) + tx + 16 * jj];
#pragma unroll
            for (int i2 = 0; i2 < 4; i2++)
                acc[i2][jj] = fma2(a2[i2], w2, acc[i2][jj]);
        }
    }

    u64 bv2[8];
#pragma unroll
    for (int jj = 0; jj < 8; jj++) bv2[jj] = dup2(bias[tx + 16 * jj]);
#pragma unroll
    for (int i2 = 0; i2 < 4; i2++)
#pragma unroll
        for (int jj = 0; jj < 8; jj++) acc[i2][jj] = add2(acc[i2][jj], bv2[jj]);

#pragma unroll
    for (int i2 = 0; i2 < 4; i2++) {
        int p = ty + 16 * i2;
#pragma unroll
        for (int e = 0; e < 2; e++) {
            int r = row0 + 2 * p + e;
            if (r >= N_NODES) continue;
#pragma unroll
            for (int jj = 0; jj < 8; jj++) {
                unsigned u = (unsigned)(e ? (acc[i2][jj] >> 32)
                                          : (acc[i2][jj] & 0xffffffffull));
                float v = __uint_as_float(u);
                if (act) v = (v > 0.f) ? v : expm1f(v);
                int c = tx + 16 * jj;
                size_t idx = (size_t)r * HID + c;
                C[idx] = v;
                if (mirror) mirror[idx] = v;
                if (do_rep) {
                    uint32_t bits = threefry_bits_0_42(0u, (uint32_t)idx);
                    float eps = bits_to_normal(bits);
                    z_out[idx] = mu_in[idx] + eps * expf(0.5f * v);
                }
            }
        }
    }
}

// ---------------- launch -----------------------------------------------------
extern "C" void kernel_launch(void* const* d_in, const int* in_sizes, int n_in,
                              void* d_out, int out_size) {
    const float* x   = (const float*)d_in[0];
    const int*   ei  = (const int*)d_in[1];
    const float* W1  = (const float*)d_in[2];
    const float* b1  = (const float*)d_in[3];
    const float* Wmu = (const float*)d_in[4];
    const float* bmu = (const float*)d_in[5];
    const float* Wlv = (const float*)d_in[6];
    const float* blv = (const float*)d_in[7];
    float* out = (float*)d_out;

    const int* src = ei;
    const int* dst = ei + N_EDGES;

    void *p_agg, *p_h1, *p_mu, *p_lv;
    cudaGetSymbolAddress(&p_agg, g_agg);
    cudaGetSymbolAddress(&p_h1,  g_h1);
    cudaGetSymbolAddress(&p_mu,  g_mu);
    cudaGetSymbolAddress(&p_lv,  g_lv);

    int big = (out_size >= 3 * NH);
    float* mu_mirror = big ? (out + NH)     : nullptr;   // mu copy into output
    float* lv_dst    = big ? (out + 2 * NH) : (float*)p_lv;

    const size_t gemm_smem = 128 * 132 * sizeof(float) + 128 * 128 * sizeof(u64);
    cudaFuncSetAttribute(k_gemm2, cudaFuncAttributeMaxDynamicSharedMemorySize,
                         (int)gemm_smem);   // 198,656 B

    const int nb_nodes = (N_NODES + 255) / 256;      // 391
    const int nb_edges = (N_EDGES + 255) / 256;      // 6250
    const int nb_agg   = (N_NODES * 64 + 255) / 256; // 25000 (2 warps/node)
    const int nb_gemm  = (N_NODES + 127) / 128;      // 782

    // preamble: degree + coalesced multi-kernel scan + CSR fill
    k_zero_cnt<<<nb_nodes, 256>>>();
    k_degree<<<nb_edges, 256>>>(dst);
    k_dinv<<<nb_nodes, 256>>>();
    k_scan1<<<nb_nodes, 256>>>();
    k_scan2<<<1, 512>>>();
    k_scan3<<<nb_nodes, 256>>>();
    k_fill<<<nb_edges, 256>>>(src, dst);

    // layer 1: agg = A_norm @ x ; h1 = elu(agg @ W1 + b1)
    k_agg<<<nb_agg, 256>>>(x, (float*)p_agg);
    k_gemm2<<<nb_gemm, 256, gemm_smem>>>((const float*)p_agg, W1, b1,
                                         (float*)p_h1, nullptr, nullptr, nullptr, 1, 0);

    // layer 2: agg = A_norm @ h1 ; mu ; lv (+fused reparam -> z)
    k_agg<<<nb_agg, 256>>>((const float*)p_h1, (float*)p_agg);
    k_gemm2<<<nb_gemm, 256, gemm_smem>>>((const float*)p_agg, Wmu, bmu,
                                         (float*)p_mu, mu_mirror, nullptr, nullptr, 0, 0);
    k_gemm2<<<nb_gemm, 256, gemm_smem>>>((const float*)p_agg, Wlv, blv,
                                         lv_dst, nullptr, (const float*)p_mu, out, 0, 1);
}

// round 8
// speedup vs baseline: 1.7336x; 1.3859x over previous
#include <cuda_runtime.h>
#include <cstdint>

#define N_NODES 100000
#define N_EDGES 1600000
#define HID     128
#define NH      12800000      // N_NODES * HID
#define NB_SCAN 391           // ceil(N_NODES/256)

// ---------------- scratch (__device__ globals: no runtime allocation) -------
__device__ float g_dinv[N_NODES];
__device__ int   g_cnt[N_NODES];
__device__ int   g_rowptr[N_NODES + 1];
__device__ int   g_cursor[N_NODES];
__device__ int2  g_ecc[N_EDGES];          // (src, coef-as-int) interleaved
__device__ int   g_bsum[512];
__device__ int   g_boff[512];
__device__ float g_agg[NH];               // P1 / agg2 buffer
__device__ float g_h1[NH];
__device__ float g_mu[NH];
__device__ float g_lv[NH];

// ---------------- degree / norm ---------------------------------------------
__global__ void k_zero_cnt() {
    int i = blockIdx.x * 256 + threadIdx.x;
    if (i < N_NODES) g_cnt[i] = 0;
}
__global__ void k_degree(const int* __restrict__ dst) {
    int i = blockIdx.x * 256 + threadIdx.x;
    if (i < N_EDGES) atomicAdd(&g_cnt[dst[i]], 1);
}
__global__ void k_dinv() {
    int i = blockIdx.x * 256 + threadIdx.x;
    if (i < N_NODES) g_dinv[i] = rsqrtf((float)g_cnt[i] + 1.0f);
}

// ---------------- CSR build: block scan + fixup ------------------------------
__global__ void k_scan1() {
    __shared__ int sh[256];
    int tid = threadIdx.x;
    int i = blockIdx.x * 256 + tid;
    int v = (i < N_NODES) ? g_cnt[i] : 0;
    sh[tid] = v;
    __syncthreads();
#pragma unroll
    for (int off = 1; off < 256; off <<= 1) {
        int t = (tid >= off) ? sh[tid - off] : 0;
        __syncthreads();
        sh[tid] += t;
        __syncthreads();
    }
    if (i < N_NODES) g_rowptr[i] = sh[tid] - v;
    if (tid == 255) g_bsum[blockIdx.x] = sh[255];
}
__global__ void k_scan2() {
    __shared__ int sh[512];
    int tid = threadIdx.x;
    int v = (tid < NB_SCAN) ? g_bsum[tid] : 0;
    sh[tid] = v;
    __syncthreads();
#pragma unroll
    for (int off = 1; off < 512; off <<= 1) {
        int t = (tid >= off) ? sh[tid - off] : 0;
        __syncthreads();
        sh[tid] += t;
        __syncthreads();
    }
    g_boff[tid] = sh[tid] - v;
    if (tid == 0) g_rowptr[N_NODES] = N_EDGES;
}
__global__ void k_scan3() {
    int i = blockIdx.x * 256 + threadIdx.x;
    if (i < N_NODES) {
        int r = g_rowptr[i] + g_boff[i >> 8];
        g_rowptr[i] = r;
        g_cursor[i] = r;
    }
}
__global__ void k_fill(const int* __restrict__ src, const int* __restrict__ dst) {
    int e = blockIdx.x * 256 + threadIdx.x;
    if (e >= N_EDGES) return;
    int d = dst[e], s = src[e];
    int pos = atomicAdd(&g_cursor[d], 1);
    float c = g_dinv[s] * g_dinv[d];
    g_ecc[pos] = make_int2(s, __float_as_int(c));
}

// ---------------- CSR aggregation: out = A_norm @ feat  (+opt bias/ELU) -----
// 2 warps per node; lane owns float2; groups of 8 edges (MLP=8).
__global__ __launch_bounds__(256) void k_agg(const float* __restrict__ feat,
                                             float* __restrict__ outp,
                                             const float* __restrict__ bias,
                                             int act) {
    int gw   = (blockIdx.x * 256 + threadIdx.x) >> 5;
    int node = gw >> 1;
    int half = gw & 1;
    int lane = threadIdx.x & 31;
    if (node >= N_NODES) return;

    int beg = g_rowptr[node];
    int end = g_rowptr[node + 1];
    float di = g_dinv[node];
    float sc = di * di;

    const float2* fp = (const float2*)feat;       // 64 float2 per node row
    int off = half * 32 + lane;

    float2 acc = fp[(size_t)node * 64 + off];
    acc.x *= sc; acc.y *= sc;

    int j = beg;
    for (; j + 8 <= end; j += 8) {
        int2 m[8];
#pragma unroll
        for (int q = 0; q < 8; q++) m[q] = g_ecc[j + q];
        float2 v[8];
#pragma unroll
        for (int q = 0; q < 8; q++)
            v[q] = fp[(size_t)m[q].x * 64 + off];
#pragma unroll
        for (int q = 0; q < 8; q++) {
            float c = __int_as_float(m[q].y);
            acc.x = fmaf(c, v[q].x, acc.x);
            acc.y = fmaf(c, v[q].y, acc.y);
        }
    }
    for (; j + 2 <= end; j += 2) {
        int2 m0 = g_ecc[j], m1 = g_ecc[j + 1];
        float2 v0 = fp[(size_t)m0.x * 64 + off];
        float2 v1 = fp[(size_t)m1.x * 64 + off];
        float c0 = __int_as_float(m0.y), c1 = __int_as_float(m1.y);
        acc.x = fmaf(c0, v0.x, acc.x); acc.y = fmaf(c0, v0.y, acc.y);
        acc.x = fmaf(c1, v1.x, acc.x); acc.y = fmaf(c1, v1.y, acc.y);
    }
    if (j < end) {
        int2 m0 = g_ecc[j];
        float2 v0 = fp[(size_t)m0.x * 64 + off];
        float c0 = __int_as_float(m0.y);
        acc.x = fmaf(c0, v0.x, acc.x); acc.y = fmaf(c0, v0.y, acc.y);
    }
    if (bias) {
        float2 b = ((const float2*)bias)[off];
        acc.x += b.x; acc.y += b.y;
    }
    if (act) {
        acc.x = (acc.x > 0.f) ? acc.x : expm1f(acc.x);
        acc.y = (acc.y > 0.f) ? acc.y : expm1f(acc.y);
    }
    ((float2*)outp)[(size_t)node * 64 + off] = acc;
}

// ------- JAX-exact RNG: PARTITIONABLE threefry2x32 + XLA erfinv -------------
__device__ __forceinline__ uint32_t rotl32(uint32_t x, int d) {
    return (x << d) | (x >> (32 - d));
}
__device__ __forceinline__ uint32_t threefry_bits_0_42(uint32_t x0, uint32_t x1) {
    const uint32_t k0 = 0u, k1 = 42u;
    const uint32_t k2 = k0 ^ k1 ^ 0x1BD11BDAu;
    x0 += k0; x1 += k1;
#define TF_RND(r) { x0 += x1; x1 = rotl32(x1, r); x1 ^= x0; }
    TF_RND(13) TF_RND(15) TF_RND(26) TF_RND(6)
    x0 += k1; x1 += k2 + 1u;
    TF_RND(17) TF_RND(29) TF_RND(16) TF_RND(24)
    x0 += k2; x1 += k0 + 2u;
    TF_RND(13) TF_RND(15) TF_RND(26) TF_RND(6)
    x0 += k0; x1 += k1 + 3u;
    TF_RND(17) TF_RND(29) TF_RND(16) TF_RND(24)
    x0 += k1; x1 += k2 + 4u;
    TF_RND(13) TF_RND(15) TF_RND(26) TF_RND(6)
    x0 += k2; x1 += k0 + 5u;
#undef TF_RND
    return x0 ^ x1;      // 32-bit XOR-fold (partitionable path)
}
__device__ __forceinline__ float erfinv_xla(float x) {
    float w = -log1pf(-x * x);
    float p;
    if (w < 5.0f) {
        w -= 2.5f;
        p = 2.81022636e-08f;
        p = fmaf(p, w, 3.43273939e-07f);
        p = fmaf(p, w, -3.5233877e-06f);
        p = fmaf(p, w, -4.39150654e-06f);
        p = fmaf(p, w, 0.00021858087f);
        p = fmaf(p, w, -0.00125372503f);
        p = fmaf(p, w, -0.00417768164f);
        p = fmaf(p, w, 0.246640727f);
        p = fmaf(p, w, 1.50140941f);
    } else {
        w = sqrtf(w) - 3.0f;
        p = -0.000200214257f;
        p = fmaf(p, w, 0.000100950558f);
        p = fmaf(p, w, 0.00134934322f);
        p = fmaf(p, w, -0.00367342844f);
        p = fmaf(p, w, 0.00573950773f);
        p = fmaf(p, w, -0.0076224613f);
        p = fmaf(p, w, 0.00943887047f);
        p = fmaf(p, w, 1.00167406f);
        p = fmaf(p, w, 2.83297682f);
    }
    return p * x;
}
__device__ __forceinline__ float bits_to_normal(uint32_t bits) {
    float u01 = __uint_as_float((bits >> 9) | 0x3f800000u) - 1.0f;
    const float lo = -0.99999994f;
    float u = fmaf(u01, 2.0f, lo);
    u = fmaxf(u, lo);
    return 1.41421356237f * erfinv_xla(u);
}

// ---------------- scalar fp32 GEMM: 64-row tile, 2 CTAs/SM -------------------
// C[M,128] = A[M,128] @ W[128,128] (+bias) (+ELU) (+mirror) (+fused reparam)
// smem: A transposed 128x68 f32 (34816 B) + W 128x128 f32 (65536 B) = 100352 B
#define GF_BIAS 1
#define GF_ELU  2
#define GF_REP  4
__global__ __launch_bounds__(256) void k_gemm(const float* __restrict__ A,
                                              const float* __restrict__ W,
                                              const float* __restrict__ bias,
                                              float* __restrict__ C,
                                              float* __restrict__ mirror,
                                              const float* __restrict__ mu_in,
                                              float* __restrict__ z_out,
                                              int flags) {
    extern __shared__ float sm[];
    float* xs = sm;                 // [k*68 + r], k<128, r<64
    float* ws = sm + 128 * 68;      // [k*128 + c]

    int row0 = blockIdx.x << 6;     // 64 rows per block

    // A tile transposed (64 rows x 128 cols)
#pragma unroll
    for (int j = 0; j < 8; j++) {
        int i  = threadIdx.x + j * 256;       // 0..2047 float4 slots
        int r  = i & 63;
        int c4 = i >> 6;                      // 0..31
        float4 v = make_float4(0.f, 0.f, 0.f, 0.f);
        if (row0 + r < N_NODES)
            v = *(const float4*)(A + (size_t)(row0 + r) * HID + (c4 << 2));
        int k = c4 << 2;
        xs[(k + 0) * 68 + r] = v.x;
        xs[(k + 1) * 68 + r] = v.y;
        xs[(k + 2) * 68 + r] = v.z;
        xs[(k + 3) * 68 + r] = v.w;
    }
    // W copy (16384 floats = 4096 float4)
#pragma unroll
    for (int j = 0; j < 16; j++) {
        int i = threadIdx.x + j * 256;
        *(float4*)(ws + (i << 2)) = *(const float4*)(W + (i << 2));
    }
    __syncthreads();

    int tx = threadIdx.x & 15;      // col group: 8 cols
    int ty = threadIdx.x >> 4;      // row group: 4 rows
    int r0 = ty << 2;
    int c0 = tx << 3;

    float acc[4][8];
#pragma unroll
    for (int i = 0; i < 4; i++)
#pragma unroll
        for (int j = 0; j < 8; j++) acc[i][j] = 0.f;

#pragma unroll 4
    for (int k = 0; k < 128; k++) {
        float a[4], w[8];
        *(float4*)(a)     = *(float4*)(xs + k * 68 + r0);
        *(float4*)(w)     = *(float4*)(ws + (k << 7) + c0);
        *(float4*)(w + 4) = *(float4*)(ws + (k << 7) + c0 + 4);
#pragma unroll
        for (int i = 0; i < 4; i++)
#pragma unroll
            for (int j = 0; j < 8; j++)
                acc[i][j] = fmaf(a[i], w[j], acc[i][j]);
    }

    float bv[8];
    if (flags & GF_BIAS) {
        *(float4*)(bv)     = *(const float4*)(bias + c0);
        *(float4*)(bv + 4) = *(const float4*)(bias + c0 + 4);
    } else {
#pragma unroll
        for (int j = 0; j < 8; j++) bv[j] = 0.f;
    }

#pragma unroll
    for (int i = 0; i < 4; i++) {
        int r = row0 + r0 + i;
        if (r >= N_NODES) break;
        float o[8];
#pragma unroll
        for (int j = 0; j < 8; j++) {
            float v = acc[i][j] + bv[j];
            if (flags & GF_ELU) v = (v > 0.f) ? v : expm1f(v);
            o[j] = v;
        }
        size_t base = (size_t)r * HID + c0;
        *(float4*)(C + base)     = *(float4*)(o);
        *(float4*)(C + base + 4) = *(float4*)(o + 4);
        if (mirror) {
            *(float4*)(mirror + base)     = *(float4*)(o);
            *(float4*)(mirror + base + 4) = *(float4*)(o + 4);
        }
        if (flags & GF_REP) {
            float zo[8];
#pragma unroll
            for (int j = 0; j < 8; j++) {
                uint32_t idx = (uint32_t)(base + j);
                uint32_t bits = threefry_bits_0_42(0u, idx);
                float eps = bits_to_normal(bits);
                zo[j] = mu_in[base + j] + eps * expf(0.5f * o[j]);
            }
            *(float4*)(z_out + base)     = *(float4*)(zo);
            *(float4*)(z_out + base + 4) = *(float4*)(zo + 4);
        }
    }
}

// ---------------- launch -----------------------------------------------------
extern "C" void kernel_launch(void* const* d_in, const int* in_sizes, int n_in,
                              void* d_out, int out_size) {
    const float* x   = (const float*)d_in[0];
    const int*   ei  = (const int*)d_in[1];
    const float* W1  = (const float*)d_in[2];
    const float* b1  = (const float*)d_in[3];
    const float* Wmu = (const float*)d_in[4];
    const float* bmu = (const float*)d_in[5];
    const float* Wlv = (const float*)d_in[6];
    const float* blv = (const float*)d_in[7];
    float* out = (float*)d_out;

    const int* src = ei;
    const int* dst = ei + N_EDGES;

    void *p_agg, *p_h1, *p_mu, *p_lv;
    cudaGetSymbolAddress(&p_agg, g_agg);
    cudaGetSymbolAddress(&p_h1,  g_h1);
    cudaGetSymbolAddress(&p_mu,  g_mu);
    cudaGetSymbolAddress(&p_lv,  g_lv);

    int big = (out_size >= 3 * NH);
    float* mu_mirror = big ? (out + NH)     : nullptr;
    float* lv_dst    = big ? (out + 2 * NH) : (float*)p_lv;

    const size_t gemm_smem = (128 * 68 + 128 * 128) * sizeof(float);  // 100,352 B
    cudaFuncSetAttribute(k_gemm, cudaFuncAttributeMaxDynamicSharedMemorySize,
                         (int)gemm_smem);

    const int nb_nodes = (N_NODES + 255) / 256;      // 391
    const int nb_edges = (N_EDGES + 255) / 256;      // 6250
    const int nb_agg   = (N_NODES * 64 + 255) / 256; // 25000 (2 warps/node)
    const int nb_gemm  = (N_NODES + 63) / 64;        // 1563

    // idx 0-2: degree prep
    k_zero_cnt<<<nb_nodes, 256>>>();
    k_degree<<<nb_edges, 256>>>(dst);
    k_dinv<<<nb_nodes, 256>>>();

    // idx 3 (PROFILED): P1 = X @ W1  (bias/ELU deferred to agg epilogue)
    k_gemm<<<nb_gemm, 256, gemm_smem>>>(x, W1, nullptr, (float*)p_agg,
                                        nullptr, nullptr, nullptr, 0);

    // idx 4-7: CSR build
    k_scan1<<<nb_nodes, 256>>>();
    k_scan2<<<1, 512>>>();
    k_scan3<<<nb_nodes, 256>>>();
    k_fill<<<nb_edges, 256>>>(src, dst);

    // idx 8: h1 = elu(A_norm @ P1 + b1)
    k_agg<<<nb_agg, 256>>>((const float*)p_agg, (float*)p_h1, b1, 1);

    // idx 9: agg2 = A_norm @ h1
    k_agg<<<nb_agg, 256>>>((const float*)p_h1, (float*)p_agg, nullptr, 0);

    // idx 10: mu = agg2 @ Wmu + bmu  (scratch + mirrored to out)
    k_gemm<<<nb_gemm, 256, gemm_smem>>>((const float*)p_agg, Wmu, bmu,
                                        (float*)p_mu, mu_mirror,
                                        nullptr, nullptr, GF_BIAS);

    // idx 11: lv = agg2 @ Wlv + blv ; z = mu + eps*exp(0.5*lv)
    k_gemm<<<nb_gemm, 256, gemm_smem>>>((const float*)p_agg, Wlv, blv,
                                        lv_dst, nullptr,
                                        (const float*)p_mu, out,
                                        GF_BIAS | GF_REP);
}